// round 16
// baseline (speedup 1.0000x reference)
#include <cuda_runtime.h>
#include <cuda_fp16.h>
#include <math.h>
#include <stdint.h>

// ---------------- problem constants ----------------
#define N_NODE 2000
#define NP     2048
#define BATCH  64
#define CC     64
#define MROWS  (BATCH*CC)    // 4096
#define DM     2048
#define IN_D   7
#define KW     49
#define ND     40
#define ALPHA_C 0.05f
#define BETA_C  0.95f

// mix GEMM tiling: CTA 256Mx128N, 512 thr, KC=64, 4 stages
#define NCHUNK  32
#define TILE_M  256
#define TILE_N  128
#define A_BYTES (256 * 128)
#define B_BYTES (128 * 128)
#define OFF_AH  0
#define OFF_BH  (A_BYTES)
#define STAGE_BYTES (A_BYTES + B_BYTES)   // 49152
#define NSTAGE  4
#define MIX_SMEM (NSTAGE * STAGE_BYTES)   // 196608
#define MT_M    (MROWS / TILE_M)          // 16 m-blocks
#define MT_N    (NP / TILE_N)             // 16 n-blocks
#define TILES_PER_LEVEL (MT_M * MT_N)     // 256
#define TOTAL_TASKS (3 * TILES_PER_LEVEL) // 768
#define MIX_GRID 148

// mlp GEMM smem layout
#define MLP_A_HI   0
#define MLP_A_LO   32768
#define MLP_B_BASE 65536
#define MLP_B_STG  16384
#define MLP_SMEM   98304

// conv GEMM smem layout
#define CV_A_STG   16384
#define CV_A_VAR   8192
#define CV_B_STG   16384
#define CV_A0      0
#define CV_B0      (2 * CV_A_STG)
#define CV_XW      (CV_B0 + 2 * CV_B_STG)
#define CV_SMEM    (CV_XW + 2 * 384)

// adj
#define ADJ_R   8
#define ADJ_BLOCKS (NP / ADJ_R)
#define ADJ_SMEM (ADJ_R * NP * 4)

// lin GEMM
#define LIN_TN  32
#define LIN_A_BYTES (64 * 128)
#define LIN_B_BYTES (LIN_TN * 128)
#define LIN_STG (LIN_A_BYTES + LIN_B_BYTES)
#define LIN_SMEM (2 * LIN_STG)

// prep1 block ranges
#define PREP_W 7
#define PREP_X 448
#define PREP_M 64
#define PREP1_BLOCKS (PREP_W + PREP_X + PREP_M)

// ---------------- scratch ----------------
__device__ __half  g_Ahi[4 * MROWS * NP];
__device__ __half  g_Alo[MROWS * NP];
__device__ __half  g_Bh[NP * NP];
__device__ __half  g_Whi[IN_D * CC * 64];
__device__ __half  g_Wlo[IN_D * CC * 64];
__device__ __half  g_Wl[NP * NP];
__device__ __half  g_Mhi[CC * 256];
__device__ __half  g_Mlo[CC * 256];
__device__ __half  g_Xh[BATCH * IN_D * DM + 128];
__device__ __half  g_Sh[BATCH * NP];
__device__ float   g_Y[BATCH * DM];
__device__ int     g_task;
__device__ int     g_done[3][MT_M];

// ---------------- helpers ----------------
__device__ __forceinline__ uint32_t smem_u32(const void* p) {
    uint32_t a;
    asm("{ .reg .u64 t; cvta.to.shared.u64 t, %1; cvt.u32.u64 %0, t; }" : "=r"(a) : "l"(p));
    return a;
}
__device__ __forceinline__ void cpa16(uint32_t s, const void* g) {
    asm volatile("cp.async.cg.shared.global [%0], [%1], 16;" :: "r"(s), "l"(g));
}
#define CPA_COMMIT() asm volatile("cp.async.commit_group;" ::: "memory")
#define CPA_WAIT(n)  asm volatile("cp.async.wait_group %0;" :: "n"(n) : "memory")

__device__ __forceinline__ void ldsm4(uint32_t* r, uint32_t addr) {
    asm volatile("ldmatrix.sync.aligned.m8n8.x4.shared.b16 {%0,%1,%2,%3}, [%4];"
                 : "=r"(r[0]), "=r"(r[1]), "=r"(r[2]), "=r"(r[3]) : "r"(addr));
}
__device__ __forceinline__ void ldsm4t(uint32_t* r, uint32_t addr) {
    asm volatile("ldmatrix.sync.aligned.m8n8.x4.trans.shared.b16 {%0,%1,%2,%3}, [%4];"
                 : "=r"(r[0]), "=r"(r[1]), "=r"(r[2]), "=r"(r[3]) : "r"(addr));
}
__device__ __forceinline__ void mma16816(float* d, const uint32_t* a, const uint32_t* b) {
    asm volatile("mma.sync.aligned.m16n8k16.row.col.f32.f16.f16.f32 "
                 "{%0,%1,%2,%3}, {%4,%5,%6,%7}, {%8,%9}, {%0,%1,%2,%3};"
                 : "+f"(d[0]), "+f"(d[1]), "+f"(d[2]), "+f"(d[3])
                 : "r"(a[0]), "r"(a[1]), "r"(a[2]), "r"(a[3]), "r"(b[0]), "r"(b[1]));
}
__device__ __forceinline__ void fp16_split(float v, __half& hi, __half& lo) {
    hi = __float2half_rn(v);
    lo = __float2half_rn(v - __half2float(hi));
}
__device__ __forceinline__ float gelu_exact(float v) {
    return 0.5f * v * (1.f + erff(v * 0.70710678118654752f));
}

// ---------------- kernel 0a: prep1 (conv w, x, w_mlp) + reset counters ----------------
__global__ void k_prep1(const float* __restrict__ w_start,
                        const float* __restrict__ x,
                        const float* __restrict__ wmlp) {
    int bid = blockIdx.x;
    int tid = threadIdx.x;
    if (bid == 0) {                       // reset task-queue state each replay
        if (tid == 0) g_task = 0;
        if (tid < 3 * MT_M) ((int*)g_done)[tid] = 0;
    }
    if (bid < PREP_W) {
        int ci = bid;
        for (int idx = tid; idx < CC * 64; idx += 256) {
            int co = idx >> 6, t = idx & 63;
            float v = (t < KW) ? w_start[co * (IN_D * KW) + ci * KW + t] : 0.f;
            __half h, l; fp16_split(v, h, l);
            g_Whi[ci * CC * 64 + idx] = h;
            g_Wlo[ci * CC * 64 + idx] = l;
        }
    } else if (bid < PREP_W + PREP_X) {
        int row = bid - PREP_W;
        size_t base = (size_t)row * DM;
        for (int i = tid; i < DM; i += 256)
            g_Xh[base + i] = __float2half_rn(x[base + i]);
        if (row == PREP_X - 1 && tid < 128)
            g_Xh[(size_t)BATCH * IN_D * DM + tid] = __float2half(0.f);
    } else {
        int o = bid - PREP_W - PREP_X;
        for (int i = tid; i < 256; i += 256) {
            float v = wmlp[o * 256 + i];
            __half h, l; fp16_split(v, h, l);
            g_Mhi[o * 256 + i] = h;
            g_Mlo[o * 256 + i] = l;
        }
    }
}

// ---------------- kernel 0b: prep w_lin ----------------
__global__ void k_prepl(const float* __restrict__ wlin) {
    int d = blockIdx.x;
    for (int w = threadIdx.x; w < NP; w += 256) {
        float v = (w < N_NODE) ? wlin[(size_t)d * N_NODE + w] : 0.f;
        g_Wl[(size_t)d * NP + w] = __float2half_rn(v);
    }
}

// ---------------- kernel 1: adjacency, 8 rows per CTA ----------------
__global__ void k_adj(const float* __restrict__ E1, const float* __restrict__ E2) {
    extern __shared__ float z[];
    __shared__ float e1s[ADJ_R][ND];
    __shared__ float red[256];
    __shared__ float srow[ADJ_R];
    int tid = threadIdx.x;
    int r0 = blockIdx.x * ADJ_R;

    if (r0 >= N_NODE) {
        for (int r = 0; r < ADJ_R; r++) {
            int v = r0 + r;
            if (v < NP)
                for (int w = tid; w < NP; w += 256) g_Bh[(size_t)v * NP + w] = __float2half(0.f);
        }
        return;
    }

    for (int idx = tid; idx < ADJ_R * ND; idx += 256)
        e1s[idx / ND][idx % ND] = E1[(r0 + idx / ND) * ND + idx % ND];
    __syncthreads();

    float lmax[ADJ_R];
#pragma unroll
    for (int r = 0; r < ADJ_R; r++) lmax[r] = -1e30f;

    for (int w = tid; w < N_NODE; w += 256) {
        float acc[ADJ_R];
#pragma unroll
        for (int r = 0; r < ADJ_R; r++) acc[r] = 0.f;
#pragma unroll 8
        for (int k = 0; k < ND; k++) {
            float e2 = E2[k * N_NODE + w];
#pragma unroll
            for (int r = 0; r < ADJ_R; r++) acc[r] += e1s[r][k] * e2;
        }
#pragma unroll
        for (int r = 0; r < ADJ_R; r++) {
            float v = fmaxf(acc[r], 0.f);
            z[r * NP + w] = v;
            lmax[r] = fmaxf(lmax[r], v);
        }
    }
#pragma unroll
    for (int r = 0; r < ADJ_R; r++) {
        red[tid] = lmax[r]; __syncthreads();
        for (int s = 128; s > 0; s >>= 1) { if (tid < s) red[tid] = fmaxf(red[tid], red[tid + s]); __syncthreads(); }
        if (tid == 0) srow[r] = red[0];
        __syncthreads();
    }
    float lsum[ADJ_R];
#pragma unroll
    for (int r = 0; r < ADJ_R; r++) lsum[r] = 0.f;
    for (int w = tid; w < N_NODE; w += 256) {
#pragma unroll
        for (int r = 0; r < ADJ_R; r++) {
            float e = __expf(z[r * NP + w] - srow[r]);
            z[r * NP + w] = e;
            lsum[r] += e;
        }
    }
#pragma unroll
    for (int r = 0; r < ADJ_R; r++) {
        red[tid] = lsum[r]; __syncthreads();
        for (int s = 128; s > 0; s >>= 1) { if (tid < s) red[tid] += red[tid + s]; __syncthreads(); }
        if (tid == 0) srow[r] = 0.5f / red[0];
        __syncthreads();
    }
    for (int w = tid; w < NP; w += 256) {
#pragma unroll
        for (int r = 0; r < ADJ_R; r++) {
            int v = r0 + r;
            float val = (w < N_NODE) ? (z[r * NP + w] * srow[r] + ((w == v) ? 0.5f : 0.f)) : 0.f;
            g_Bh[(size_t)v * NP + w] = __float2half_rn(val);
        }
    }
}

// ---------------- kernel 2: start conv on HMMA (2-product) ----------------
__global__ __launch_bounds__(256, 2) void k_conv_mma(const float* __restrict__ bias) {
    extern __shared__ char smem[];
    const uint32_t sbase = smem_u32(smem);
    __half* xw = (__half*)(smem + CV_XW);
    const int tid = threadIdx.x;
    const int wid = tid >> 5, lane = tid & 31;
    const int wm = wid >> 1;
    const int wn = wid & 1;
    const int b  = blockIdx.y;
    const int n0 = blockIdx.x * 128;

#define CV_LOAD_A(ci, stg) do {                                                      \
    _Pragma("unroll")                                                                \
    for (int i = 0; i < 2; i++) {                                                    \
        int idx = tid + i * 256;                                                     \
        int co = idx >> 3, s = idx & 7;                                              \
        uint32_t dst = sbase + CV_A0 + (stg) * CV_A_STG + co * 128 +                 \
                       ((uint32_t)(s ^ (co & 7)) << 4);                              \
        cpa16(dst,            (const char*)(g_Whi + (ci) * CC * 64 + co * 64 + s * 8)); \
        cpa16(dst + CV_A_VAR, (const char*)(g_Wlo + (ci) * CC * 64 + co * 64 + s * 8)); \
    }                                                                                \
} while (0)

#define CV_LOAD_XW(ci, stg) do {                                                     \
    if (tid < 24)                                                                    \
        cpa16(sbase + CV_XW + (stg) * 384 + tid * 16,                                \
              (const char*)(g_Xh + (size_t)b * IN_D * DM + (ci) * DM + n0) + tid * 16); \
} while (0)

#define CV_BUILD_B(stg) do {                                                         \
    const __half* xwp = xw + (stg) * 192;                                            \
    _Pragma("unroll")                                                                \
    for (int i = 0; i < 16; i++) {                                                   \
        int idx = tid + i * 256;                                                     \
        int t = idx >> 6, j2 = idx & 63;                                             \
        int n = j2 * 2;                                                              \
        __half2 hh(xwp[t + n], xwp[t + n + 1]);                                      \
        int s = n >> 3;                                                              \
        uint32_t off = t * 256 + ((uint32_t)(s ^ (t & 7)) << 4) + (j2 & 3) * 4;      \
        *(uint32_t*)(smem + CV_B0 + (stg) * CV_B_STG + off) = *reinterpret_cast<uint32_t*>(&hh); \
    }                                                                                \
} while (0)

    float acc[8][4];
#pragma unroll
    for (int in = 0; in < 8; in++)
#pragma unroll
        for (int q = 0; q < 4; q++) acc[in][q] = 0.f;

    const int a_row = wm * 16 + (lane & 15);
    const int a_jl  = lane >> 4;
    const int b_kl  = ((lane >> 3) & 1) * 8 + (lane & 7);
    const int b_nl  = lane >> 4;

    CV_LOAD_A(0, 0);
    CV_LOAD_XW(0, 0);
    CPA_COMMIT();
    CPA_WAIT(0);
    __syncthreads();
    CV_BUILD_B(0);
    __syncthreads();

    for (int c = 0; c < IN_D; c++) {
        int stg = c & 1, nstg = (c + 1) & 1;
        if (c + 1 < IN_D) { CV_LOAD_A(c + 1, nstg); CV_LOAD_XW(c + 1, nstg); CPA_COMMIT(); }

        uint32_t astg = sbase + CV_A0 + stg * CV_A_STG;
        uint32_t bstg = sbase + CV_B0 + stg * CV_B_STG;
#pragma unroll
        for (int ks = 0; ks < 4; ks++) {
            uint32_t ah[4], al[4], bh[4][4];
            {
                int s = 2 * ks + a_jl;
                uint32_t off = (uint32_t)a_row * 128 + ((uint32_t)(s ^ (a_row & 7)) << 4);
                ldsm4(ah, astg + off);
                ldsm4(al, astg + CV_A_VAR + off);
            }
            int krow = ks * 16 + b_kl;
            uint32_t koff = (uint32_t)krow * 256;
            uint32_t kx = (uint32_t)(krow & 7);
#pragma unroll
            for (int q = 0; q < 4; q++) {
                int ns = wn * 8 + 2 * q + b_nl;
                uint32_t off = koff + ((uint32_t)(ns ^ kx) << 4);
                ldsm4t(bh[q], bstg + off);
            }
#pragma unroll
            for (int p = 0; p < 2; p++) {
#pragma unroll
                for (int in = 0; in < 8; in++) {
                    const uint32_t* af = (p == 1) ? al : ah;
                    mma16816(acc[in], af, &bh[in >> 1][(in & 1) * 2]);
                }
            }
        }
        if (c + 1 < IN_D) {
            CPA_WAIT(0);
            __syncthreads();
            CV_BUILD_B(nstg);
            __syncthreads();
        }
    }

    const int o0 = wm * 16 + (lane >> 2);
    const int o1 = o0 + 8;
    const float b0v = bias[o0], b1v = bias[o1];
#pragma unroll
    for (int in = 0; in < 8; in++) {
        int n = n0 + wn * 64 + in * 8 + (lane & 3) * 2;
        bool ok = (n < N_NODE);
        float v00 = ok ? (acc[in][0] + b0v) : 0.f;
        float v01 = ok ? (acc[in][1] + b0v) : 0.f;
        float v10 = ok ? (acc[in][2] + b1v) : 0.f;
        float v11 = ok ? (acc[in][3] + b1v) : 0.f;
        size_t r0 = (size_t)(b * CC + o0) * NP + n;
        size_t r1 = (size_t)(b * CC + o1) * NP + n;
        __half h0, l0, h1, l1;
        fp16_split(v00, h0, l0); fp16_split(v01, h1, l1);
        *(__half2*)(g_Ahi + r0) = __half2(h0, h1);
        *(__half2*)(g_Alo + r0) = __half2(l0, l1);
        fp16_split(v10, h0, l0); fp16_split(v11, h1, l1);
        *(__half2*)(g_Ahi + r1) = __half2(h0, h1);
        *(__half2*)(g_Alo + r1) = __half2(l0, l1);
    }
#undef CV_LOAD_A
#undef CV_LOAD_XW
#undef CV_BUILD_B
}

// ---------------- kernel 3: FUSED persistent mixprop (3 levels, task queue) --------
__global__ __launch_bounds__(512, 1) void k_mix_fused() {
    extern __shared__ char smem[];
    const uint32_t sbase = smem_u32(smem);
    __shared__ int s_task;

    const int tid = threadIdx.x;
    const int wid = tid >> 5, lane = tid & 31;
    const int wm = wid >> 2;
    const int wn = wid & 3;

    const int ar = tid >> 1;
    const int as_ = (tid & 1) * 4;
    const uint32_t aswz = (uint32_t)(ar & 7);
    const int br = tid >> 2;
    const int bs_ = (tid & 3) * 2;
    const uint32_t bswz = (uint32_t)(br & 7);

    const int a_row_l = (lane & 15);
    const int a_jl = lane >> 4;
    const int b_row_l = ((lane >> 4) << 3) + (lane & 7);
    const int b_jl = (lane >> 3) & 1;

    for (;;) {
        if (tid == 0) s_task = atomicAdd(&g_task, 1);
        __syncthreads();
        const int t = s_task;
        if (t >= TOTAL_TASKS) return;
        const int level = t >> 8;            // /TILES_PER_LEVEL
        const int tile = t & 255;
        const int tm = tile >> 4;
        const int m0 = tm * TILE_M;
        const int n0 = (tile & 15) * TILE_N;

        if (level > 0) {
            if (tid == 0) {
                while (atomicAdd(&g_done[level - 1][tm], 0) < MT_N) __nanosleep(128);
            }
            __threadfence();
            __syncthreads();
        }

        const __half* Ahi = g_Ahi + (size_t)level * MROWS * NP;
        const char* gA = (const char*)(Ahi + (size_t)(m0 + ar) * NP) + as_ * 16;
        const char* gB = (const char*)(g_Bh + (size_t)(n0 + br) * NP) + bs_ * 16;

#define LOAD_CHUNK(cidx, buf) do {                                                   \
    uint32_t sb = sbase + (buf) * STAGE_BYTES;                                       \
    size_t go = (size_t)(cidx) * 128;                                                \
    uint32_t sa = sb + OFF_AH + ar * 128;                                            \
    _Pragma("unroll")                                                                \
    for (int j = 0; j < 4; j++) {                                                    \
        uint32_t so = ((uint32_t)(as_ + j) ^ aswz) << 4;                             \
        cpa16(sa + so, gA + go + j * 16);                                            \
    }                                                                                \
    uint32_t sbb = sb + OFF_BH + br * 128;                                           \
    _Pragma("unroll")                                                                \
    for (int j = 0; j < 2; j++) {                                                    \
        uint32_t so = ((uint32_t)(bs_ + j) ^ bswz) << 4;                             \
        cpa16(sbb + so, gB + go + j * 16);                                           \
    }                                                                                \
} while (0)

        float acc[4][4][4];
#pragma unroll
        for (int im = 0; im < 4; im++)
#pragma unroll
            for (int in = 0; in < 4; in++)
#pragma unroll
                for (int q = 0; q < 4; q++) acc[im][in][q] = 0.f;

#define COMPUTE_CHUNK(buf) do {                                                      \
    uint32_t sb = sbase + (buf) * STAGE_BYTES;                                       \
    _Pragma("unroll")                                                                \
    for (int ks = 0; ks < 4; ks++) {                                                 \
        uint32_t ah[4][4], bh[2][4];                                                 \
        _Pragma("unroll")                                                            \
        for (int im = 0; im < 4; im++) {                                             \
            int row = wm * 64 + im * 16 + a_row_l;                                   \
            uint32_t off = (uint32_t)row * 128 +                                     \
                           ((uint32_t)((2 * ks + a_jl) ^ (row & 7)) << 4);           \
            ldsm4(ah[im], sb + OFF_AH + off);                                        \
        }                                                                            \
        _Pragma("unroll")                                                            \
        for (int inb = 0; inb < 2; inb++) {                                          \
            int row = wn * 32 + inb * 16 + b_row_l;                                  \
            uint32_t off = (uint32_t)row * 128 +                                     \
                           ((uint32_t)((2 * ks + b_jl) ^ (row & 7)) << 4);           \
            ldsm4(bh[inb], sb + OFF_BH + off);                                       \
        }                                                                            \
        _Pragma("unroll")                                                            \
        for (int im = 0; im < 4; im++)                                               \
            _Pragma("unroll")                                                        \
            for (int in = 0; in < 4; in++)                                           \
                mma16816(acc[im][in], ah[im], &bh[in >> 1][(in & 1) * 2]);           \
    }                                                                                \
} while (0)

        LOAD_CHUNK(0, 0); CPA_COMMIT();
        LOAD_CHUNK(1, 1); CPA_COMMIT();

        for (int cc = 0; cc < NCHUNK; cc += 2) {
            __syncthreads();
            if (cc + 2 < NCHUNK) {
                LOAD_CHUNK(cc + 2, (cc + 2) & 3); CPA_COMMIT();
                LOAD_CHUNK(cc + 3, (cc + 3) & 3); CPA_COMMIT();
                CPA_WAIT(2);
            } else {
                CPA_WAIT(0);
            }
            COMPUTE_CHUNK(cc & 3);
            COMPUTE_CHUNK((cc + 1) & 3);
        }

        // epilogue: C = ALPHA*(h0 hi+lo) + BETA*acc -> fp16 hi
        const __half* Xh = g_Ahi;
        const __half* Xl = g_Alo;
        __half* Hh = g_Ahi + (size_t)(level + 1) * MROWS * NP;

#pragma unroll
        for (int im = 0; im < 4; im++) {
#pragma unroll
            for (int half = 0; half < 2; half++) {
                int m = m0 + wm * 64 + im * 16 + (lane >> 2) + half * 8;
                size_t rowo = (size_t)m * NP;
#pragma unroll
                for (int in = 0; in < 4; in++) {
                    int n = n0 + wn * 32 + in * 8 + (lane & 3) * 2;
                    float d0 = acc[im][in][half * 2 + 0];
                    float d1 = acc[im][in][half * 2 + 1];
                    __half2 xh = *(const __half2*)(Xh + rowo + n);
                    __half2 xl = *(const __half2*)(Xl + rowo + n);
                    float x0 = __half2float(xh.x) + __half2float(xl.x);
                    float x1 = __half2float(xh.y) + __half2float(xl.y);
                    float o0 = ALPHA_C * x0 + BETA_C * d0;
                    float o1 = ALPHA_C * x1 + BETA_C * d1;
                    *(__half2*)(Hh + rowo + n) =
                        __half2(__float2half_rn(o0), __float2half_rn(o1));
                }
            }
        }

        __threadfence();
        __syncthreads();
        if (tid == 0) atomicAdd(&g_done[level][tm], 1);
        __syncthreads();
#undef LOAD_CHUNK
#undef COMPUTE_CHUNK
    }
}

// ---------------- kernel 4: MLP on HMMA (2-product) + GELU + end dot ----------------
__global__ __launch_bounds__(256) void k_mlp_mma(const float* __restrict__ bmlp,
                                                 const float* __restrict__ wend,
                                                 const float* __restrict__ bend) {
    extern __shared__ char smem[];
    __shared__ float red[4][128];
    const uint32_t sbase = smem_u32(smem);
    const int tid = threadIdx.x;
    const int wid = tid >> 5, lane = tid & 31;
    const int wm = wid >> 1;
    const int wn = wid & 1;
    const int b  = blockIdx.y;
    const int n0 = blockIdx.x * 128;

#pragma unroll
    for (int i = 0; i < 8; i++) {
        int idx = tid + i * 256;
        int o = idx >> 5, s = idx & 31;
        uint32_t phys = (uint32_t)(s ^ (o & 15));
        uint32_t dst = sbase + o * 512 + phys * 16;
        cpa16(dst + MLP_A_HI, (const char*)(g_Mhi + o * 256 + s * 8));
        cpa16(dst + MLP_A_LO, (const char*)(g_Mlo + o * 256 + s * 8));
    }

#define LOAD_BCH(chunk, stg) do {                                                        \
    const __half* HBh = g_Ahi + ((size_t)(chunk) * MROWS + b * 64) * NP + n0;            \
    _Pragma("unroll")                                                                    \
    for (int i = 0; i < 4; i++) {                                                        \
        int idx = tid + i * 256;                                                         \
        int k = idx >> 4, s = idx & 15;                                                  \
        uint32_t phys = (uint32_t)(s ^ (k & 7));                                         \
        uint32_t dst = sbase + MLP_B_BASE + (stg) * MLP_B_STG + k * 256 + phys * 16;     \
        cpa16(dst, (const char*)HBh + (size_t)k * NP * 2 + s * 16);                      \
    }                                                                                    \
} while (0)

    float acc[8][4];
#pragma unroll
    for (int in = 0; in < 8; in++)
#pragma unroll
        for (int q = 0; q < 4; q++) acc[in][q] = 0.f;

    const int a_row = wm * 16 + (lane & 15);
    const int a_jl  = lane >> 4;
    const int b_kl  = ((lane >> 3) & 1) * 8 + (lane & 7);
    const int b_nl  = lane >> 4;

    LOAD_BCH(0, 0); CPA_COMMIT();

    for (int chunk = 0; chunk < 4; chunk++) {
        CPA_WAIT(0);
        __syncthreads();
        if (chunk < 3) { LOAD_BCH(chunk + 1, (chunk + 1) & 1); CPA_COMMIT(); }
        uint32_t bstg = sbase + MLP_B_BASE + (chunk & 1) * MLP_B_STG;

#pragma unroll
        for (int ks = 0; ks < 4; ks++) {
            int ksg = chunk * 4 + ks;
            uint32_t ah[4], al[4], bh[4][4];
            {
                int s = 2 * ksg + a_jl;
                uint32_t off = (uint32_t)a_row * 512 + ((uint32_t)(s ^ (a_row & 15)) << 4);
                ldsm4(ah, sbase + MLP_A_HI + off);
                ldsm4(al, sbase + MLP_A_LO + off);
            }
            int krow = ks * 16 + b_kl;
            uint32_t koff = (uint32_t)krow * 256;
            uint32_t kx = (uint32_t)(krow & 7);
#pragma unroll
            for (int q = 0; q < 4; q++) {
                int ns = wn * 8 + 2 * q + b_nl;
                uint32_t off = koff + ((uint32_t)(ns ^ kx) << 4);
                ldsm4t(bh[q], bstg + off);
            }
#pragma unroll
            for (int p = 0; p < 2; p++) {
#pragma unroll
                for (int in = 0; in < 8; in++) {
                    const uint32_t* af = (p == 1) ? al : ah;
                    mma16816(acc[in], af, &bh[in >> 1][(in & 1) * 2]);
                }
            }
        }
        __syncthreads();
    }

    const int o0 = wm * 16 + (lane >> 2);
    const int o1 = o0 + 8;
    const float bm0 = bmlp[o0], bm1 = bmlp[o1];
    const float we0 = wend[o0], we1 = wend[o1];

#pragma unroll
    for (int in = 0; in < 8; in++) {
        float g00 = gelu_exact(acc[in][0] + bm0);
        float g01 = gelu_exact(acc[in][1] + bm0);
        float g10 = gelu_exact(acc[in][2] + bm1);
        float g11 = gelu_exact(acc[in][3] + bm1);
        float p0 = we0 * g00 + we1 * g10;
        float p1 = we0 * g01 + we1 * g11;
#pragma unroll
        for (int d = 4; d <= 16; d <<= 1) {
            p0 += __shfl_xor_sync(0xFFFFFFFF, p0, d);
            p1 += __shfl_xor_sync(0xFFFFFFFF, p1, d);
        }
        if (lane < 4) {
            red[wm][wn * 64 + in * 8 + lane * 2 + 0] = p0;
            red[wm][wn * 64 + in * 8 + lane * 2 + 1] = p1;
        }
    }
    __syncthreads();
    if (tid < 128) {
        int n = n0 + tid;
        float s = bend[0] + red[0][tid] + red[1][tid] + red[2][tid] + red[3][tid];
        g_Sh[(size_t)b * NP + n] = __float2half_rn((n < N_NODE) ? s : 0.f);
    }
#undef LOAD_BCH
}

// ---------------- kernel 5: final linear on HMMA ----------------
__global__ __launch_bounds__(256) void k_lin_mma(const float* __restrict__ blin) {
    extern __shared__ char smem[];
    const uint32_t sbase = smem_u32(smem);
    const int tid = threadIdx.x;
    const int wid = tid >> 5, lane = tid & 31;
    const int wm = wid >> 1;
    const int wn = wid & 1;
    const int n0 = blockIdx.x * LIN_TN;

#define LIN_LOAD(cidx, stg) do {                                                     \
    _Pragma("unroll")                                                                \
    for (int i = 0; i < 2; i++) {                                                    \
        int idx = tid + i * 256;                                                     \
        int row = idx >> 3, s = idx & 7;                                             \
        uint32_t so = ((uint32_t)(s ^ (row & 7)) << 4);                              \
        cpa16(sbase + (stg) * LIN_STG + row * 128 + so,                              \
              (const char*)(g_Sh + (size_t)row * NP) + (size_t)(cidx) * 128 + s * 16); \
    }                                                                                \
    {                                                                                \
        int row = tid >> 3, s = tid & 7;                                             \
        uint32_t so = ((uint32_t)(s ^ (row & 7)) << 4);                              \
        cpa16(sbase + (stg) * LIN_STG + LIN_A_BYTES + row * 128 + so,                \
              (const char*)(g_Wl + (size_t)(n0 + row) * NP) + (size_t)(cidx) * 128 + s * 16); \
    }                                                                                \
} while (0)

    float acc[2][4];
#pragma unroll
    for (int in = 0; in < 2; in++)
#pragma unroll
        for (int q = 0; q < 4; q++) acc[in][q] = 0.f;

    const int a_row_l = (lane & 15);
    const int a_jl = lane >> 4;
    const int b_row_l = ((lane >> 4) << 3) + (lane & 7);
    const int b_jl = (lane >> 3) & 1;

    LIN_LOAD(0, 0); CPA_COMMIT();

    for (int c = 0; c < 32; c++) {
        CPA_WAIT(0);
        __syncthreads();
        if (c + 1 < 32) { LIN_LOAD(c + 1, (c + 1) & 1); CPA_COMMIT(); }
        uint32_t astg = sbase + (c & 1) * LIN_STG;
        uint32_t bstg = astg + LIN_A_BYTES;
#pragma unroll
        for (int ks = 0; ks < 4; ks++) {
            uint32_t ah[4], bh[4];
            {
                int row = wm * 16 + a_row_l;
                uint32_t off = (uint32_t)row * 128 +
                               ((uint32_t)((2 * ks + a_jl) ^ (row & 7)) << 4);
                ldsm4(ah, astg + off);
            }
            {
                int row = wn * 16 + b_row_l;
                uint32_t off = (uint32_t)row * 128 +
                               ((uint32_t)((2 * ks + b_jl) ^ (row & 7)) << 4);
                ldsm4(bh, bstg + off);
            }
#pragma unroll
            for (int in = 0; in < 2; in++)
                mma16816(acc[in], ah, &bh[in * 2]);
        }
        __syncthreads();
    }

#pragma unroll
    for (int in = 0; in < 2; in++) {
        int d = n0 + wn * 16 + in * 8 + (lane & 3) * 2;
        int b0 = wm * 16 + (lane >> 2), b1 = b0 + 8;
        float bl0 = blin[d], bl1 = blin[d + 1];
        g_Y[(size_t)b0 * DM + d]     = acc[in][0] + bl0;
        g_Y[(size_t)b0 * DM + d + 1] = acc[in][1] + bl1;
        g_Y[(size_t)b1 * DM + d]     = acc[in][2] + bl0;
        g_Y[(size_t)b1 * DM + d + 1] = acc[in][3] + bl1;
    }
#undef LIN_LOAD
}

// ---------------- kernel 6: layernorm ----------------
__global__ void k_ln(const float* __restrict__ gam, const float* __restrict__ bet,
                     float* __restrict__ out) {
    int b = blockIdx.x;
    int tid = threadIdx.x;
    __shared__ float red[256];
    const float* y = g_Y + (size_t)b * DM;

    float s = 0.f;
    for (int d = tid; d < DM; d += 256) s += y[d];
    red[tid] = s; __syncthreads();
    for (int st = 128; st > 0; st >>= 1) { if (tid < st) red[tid] += red[tid + st]; __syncthreads(); }
    float mu = red[0] / DM;
    __syncthreads();

    float v = 0.f;
    for (int d = tid; d < DM; d += 256) { float t = y[d] - mu; v += t * t; }
    red[tid] = v; __syncthreads();
    for (int st = 128; st > 0; st >>= 1) { if (tid < st) red[tid] += red[tid + st]; __syncthreads(); }
    float rinv = rsqrtf(red[0] / DM + 1e-5f);

    for (int d = tid; d < DM; d += 256)
        out[(size_t)b * DM + d] = (y[d] - mu) * rinv * gam[d] + bet[d];
}

// ---------------- launch ----------------
extern "C" void kernel_launch(void* const* d_in, const int* in_sizes, int n_in,
                              void* d_out, int out_size) {
    const float* x       = (const float*)d_in[0];
    const float* nv1     = (const float*)d_in[1];
    const float* nv2     = (const float*)d_in[2];
    const float* w_start = (const float*)d_in[3];
    const float* b_start = (const float*)d_in[4];
    const float* w_mlp   = (const float*)d_in[5];
    const float* b_mlp   = (const float*)d_in[6];
    const float* w_end   = (const float*)d_in[7];
    const float* b_end   = (const float*)d_in[8];
    const float* w_lin   = (const float*)d_in[9];
    const float* b_lin   = (const float*)d_in[10];
    const float* ln_g    = (const float*)d_in[11];
    const float* ln_b    = (const float*)d_in[12];
    float* out = (float*)d_out;

    static bool init = false;
    static cudaStream_t s2;
    static cudaEvent_t e_prep, e_conv, e_lin;
    if (!init) {
        cudaStreamCreateWithFlags(&s2, cudaStreamNonBlocking);
        cudaEventCreateWithFlags(&e_prep, cudaEventDisableTiming);
        cudaEventCreateWithFlags(&e_conv, cudaEventDisableTiming);
        cudaEventCreateWithFlags(&e_lin,  cudaEventDisableTiming);
        cudaFuncSetAttribute(k_mix_fused, cudaFuncAttributeMaxDynamicSharedMemorySize, MIX_SMEM);
        cudaFuncSetAttribute(k_mlp_mma,   cudaFuncAttributeMaxDynamicSharedMemorySize, MLP_SMEM);
        cudaFuncSetAttribute(k_conv_mma,  cudaFuncAttributeMaxDynamicSharedMemorySize, CV_SMEM);
        cudaFuncSetAttribute(k_adj,       cudaFuncAttributeMaxDynamicSharedMemorySize, ADJ_SMEM);
        cudaFuncSetAttribute(k_lin_mma,   cudaFuncAttributeMaxDynamicSharedMemorySize, LIN_SMEM);
        init = true;
    }

    // stream 0: prep1(+counter reset) -> adj     stream s2: (after prep1) conv -> prepl
    k_prep1<<<PREP1_BLOCKS, 256>>>(w_start, x, w_mlp);
    cudaEventRecord(e_prep, 0);
    k_adj<<<ADJ_BLOCKS, 256, ADJ_SMEM>>>(nv1, nv2);

    cudaStreamWaitEvent(s2, e_prep, 0);
    k_conv_mma<<<dim3(NP / 128, BATCH), 256, CV_SMEM, s2>>>(b_start);
    cudaEventRecord(e_conv, s2);
    k_prepl<<<DM, 256, 0, s2>>>(w_lin);
    cudaEventRecord(e_lin, s2);

    cudaStreamWaitEvent(0, e_conv, 0);
    k_mix_fused<<<MIX_GRID, 512, MIX_SMEM>>>();
    k_mlp_mma<<<dim3(NP / 128, BATCH), 256, MLP_SMEM>>>(b_mlp, w_end, b_end);
    cudaStreamWaitEvent(0, e_lin, 0);
    k_lin_mma<<<NP / LIN_TN, 256, LIN_SMEM>>>(b_lin);
    k_ln<<<BATCH, 256>>>(ln_g, ln_b, out);
}

// round 17
// speedup vs baseline: 1.0669x; 1.0669x over previous
#include <cuda_runtime.h>
#include <cuda_fp16.h>
#include <math.h>
#include <stdint.h>

// ---------------- problem constants ----------------
#define N_NODE 2000
#define NP     2048
#define BATCH  64
#define CC     64
#define MROWS  (BATCH*CC)    // 4096
#define DM     2048
#define IN_D   7
#define KW     49
#define ND     40
#define ALPHA_C 0.05f
#define BETA_C  0.95f

// mix GEMM tiling: CTA 256Mx128N, 512 thr, KC=64 (128B rows, SW128), 4 stages
#define NCHUNK  32
#define TILE_M  256
#define TILE_N  128
#define A_BYTES (256 * 128)
#define B_BYTES (128 * 128)
#define OFF_AH  0
#define OFF_BH  (A_BYTES)
#define STAGE_BYTES (A_BYTES + B_BYTES)   // 49152
#define NSTAGE  4
#define MIX_SMEM (NSTAGE * STAGE_BYTES)   // 196608

// mlp GEMM smem layout
#define MLP_A_HI   0
#define MLP_A_LO   32768
#define MLP_B_BASE 65536
#define MLP_B_STG  16384
#define MLP_SMEM   98304

// conv GEMM smem layout
#define CV_A_STG   16384
#define CV_A_VAR   8192
#define CV_B_STG   16384
#define CV_A0      0
#define CV_B0      (2 * CV_A_STG)
#define CV_XW      (CV_B0 + 2 * CV_B_STG)
#define CV_SMEM    (CV_XW + 2 * 384)

// adj
#define ADJ_R   8
#define ADJ_BLOCKS (NP / ADJ_R)        // 256
#define ADJ_SMEM (ADJ_R * NP * 4)      // 65536

// lin GEMM
#define LIN_TN  32
#define LIN_A_BYTES (64 * 128)
#define LIN_B_BYTES (LIN_TN * 128)
#define LIN_STG (LIN_A_BYTES + LIN_B_BYTES)
#define LIN_SMEM (2 * LIN_STG)

// prep1 block ranges (w_start, x, w_mlp)
#define PREP_W 7
#define PREP_X 448
#define PREP_M 64
#define PREP1_BLOCKS (PREP_W + PREP_X + PREP_M)   // 519

// ---------------- scratch ----------------
__device__ __half  g_Ahi[4 * MROWS * NP];
__device__ __half  g_Alo[MROWS * NP];       // lo of hop0 only
__device__ __half  g_Bh[NP * NP];
__device__ __half  g_Whi[IN_D * CC * 64];
__device__ __half  g_Wlo[IN_D * CC * 64];
__device__ __half  g_Wl[NP * NP];
__device__ __half  g_Mhi[CC * 256];
__device__ __half  g_Mlo[CC * 256];
__device__ __half  g_Xh[BATCH * IN_D * DM + 128];
__device__ __half  g_Sh[BATCH * NP];
__device__ float   g_Y[BATCH * DM];

// ---------------- helpers ----------------
__device__ __forceinline__ uint32_t smem_u32(const void* p) {
    uint32_t a;
    asm("{ .reg .u64 t; cvta.to.shared.u64 t, %1; cvt.u32.u64 %0, t; }" : "=r"(a) : "l"(p));
    return a;
}
__device__ __forceinline__ void cpa16(uint32_t s, const void* g) {
    asm volatile("cp.async.cg.shared.global [%0], [%1], 16;" :: "r"(s), "l"(g));
}
#define CPA_COMMIT() asm volatile("cp.async.commit_group;" ::: "memory")
#define CPA_WAIT(n)  asm volatile("cp.async.wait_group %0;" :: "n"(n) : "memory")

__device__ __forceinline__ void ldsm4(uint32_t* r, uint32_t addr) {
    asm volatile("ldmatrix.sync.aligned.m8n8.x4.shared.b16 {%0,%1,%2,%3}, [%4];"
                 : "=r"(r[0]), "=r"(r[1]), "=r"(r[2]), "=r"(r[3]) : "r"(addr));
}
__device__ __forceinline__ void ldsm4t(uint32_t* r, uint32_t addr) {
    asm volatile("ldmatrix.sync.aligned.m8n8.x4.trans.shared.b16 {%0,%1,%2,%3}, [%4];"
                 : "=r"(r[0]), "=r"(r[1]), "=r"(r[2]), "=r"(r[3]) : "r"(addr));
}
__device__ __forceinline__ void mma16816(float* d, const uint32_t* a, const uint32_t* b) {
    asm volatile("mma.sync.aligned.m16n8k16.row.col.f32.f16.f16.f32 "
                 "{%0,%1,%2,%3}, {%4,%5,%6,%7}, {%8,%9}, {%0,%1,%2,%3};"
                 : "+f"(d[0]), "+f"(d[1]), "+f"(d[2]), "+f"(d[3])
                 : "r"(a[0]), "r"(a[1]), "r"(a[2]), "r"(a[3]), "r"(b[0]), "r"(b[1]));
}
__device__ __forceinline__ void fp16_split(float v, __half& hi, __half& lo) {
    hi = __float2half_rn(v);
    lo = __float2half_rn(v - __half2float(hi));
}
__device__ __forceinline__ float gelu_exact(float v) {
    return 0.5f * v * (1.f + erff(v * 0.70710678118654752f));
}

// ---------------- kernel 0a: prep1 (conv w, x, w_mlp) ----------------
__global__ void k_prep1(const float* __restrict__ w_start,
                        const float* __restrict__ x,
                        const float* __restrict__ wmlp) {
    int bid = blockIdx.x;
    int tid = threadIdx.x;
    if (bid < PREP_W) {
        int ci = bid;
        for (int idx = tid; idx < CC * 64; idx += 256) {
            int co = idx >> 6, t = idx & 63;
            float v = (t < KW) ? w_start[co * (IN_D * KW) + ci * KW + t] : 0.f;
            __half h, l; fp16_split(v, h, l);
            g_Whi[ci * CC * 64 + idx] = h;
            g_Wlo[ci * CC * 64 + idx] = l;
        }
    } else if (bid < PREP_W + PREP_X) {
        int row = bid - PREP_W;
        size_t base = (size_t)row * DM;
        for (int i = tid; i < DM; i += 256)
            g_Xh[base + i] = __float2half_rn(x[base + i]);
        if (row == PREP_X - 1 && tid < 128)
            g_Xh[(size_t)BATCH * IN_D * DM + tid] = __float2half(0.f);
    } else {
        int o = bid - PREP_W - PREP_X;
        for (int i = tid; i < 256; i += 256) {
            float v = wmlp[o * 256 + i];
            __half h, l; fp16_split(v, h, l);
            g_Mhi[o * 256 + i] = h;
            g_Mlo[o * 256 + i] = l;
        }
    }
}

// ---------------- kernel 0b: prep w_lin -> fp16 padded ----------------
__global__ void k_prepl(const float* __restrict__ wlin) {
    int d = blockIdx.x;
    for (int w = threadIdx.x; w < NP; w += 256) {
        float v = (w < N_NODE) ? wlin[(size_t)d * N_NODE + w] : 0.f;
        g_Wl[(size_t)d * NP + w] = __float2half_rn(v);
    }
}

// ---------------- kernel 1: adjacency, 8 rows per CTA ----------------
__global__ void k_adj(const float* __restrict__ E1, const float* __restrict__ E2) {
    extern __shared__ float z[];
    __shared__ float e1s[ADJ_R][ND];
    __shared__ float red[256];
    __shared__ float srow[ADJ_R];
    int tid = threadIdx.x;
    int r0 = blockIdx.x * ADJ_R;

    if (r0 >= N_NODE) {
        for (int r = 0; r < ADJ_R; r++) {
            int v = r0 + r;
            if (v < NP)
                for (int w = tid; w < NP; w += 256) g_Bh[(size_t)v * NP + w] = __float2half(0.f);
        }
        return;
    }

    for (int idx = tid; idx < ADJ_R * ND; idx += 256)
        e1s[idx / ND][idx % ND] = E1[(r0 + idx / ND) * ND + idx % ND];
    __syncthreads();

    float lmax[ADJ_R];
#pragma unroll
    for (int r = 0; r < ADJ_R; r++) lmax[r] = -1e30f;

    for (int w = tid; w < N_NODE; w += 256) {
        float acc[ADJ_R];
#pragma unroll
        for (int r = 0; r < ADJ_R; r++) acc[r] = 0.f;
#pragma unroll 8
        for (int k = 0; k < ND; k++) {
            float e2 = E2[k * N_NODE + w];
#pragma unroll
            for (int r = 0; r < ADJ_R; r++) acc[r] += e1s[r][k] * e2;
        }
#pragma unroll
        for (int r = 0; r < ADJ_R; r++) {
            float v = fmaxf(acc[r], 0.f);
            z[r * NP + w] = v;
            lmax[r] = fmaxf(lmax[r], v);
        }
    }
#pragma unroll
    for (int r = 0; r < ADJ_R; r++) {
        red[tid] = lmax[r]; __syncthreads();
        for (int s = 128; s > 0; s >>= 1) { if (tid < s) red[tid] = fmaxf(red[tid], red[tid + s]); __syncthreads(); }
        if (tid == 0) srow[r] = red[0];
        __syncthreads();
    }
    float lsum[ADJ_R];
#pragma unroll
    for (int r = 0; r < ADJ_R; r++) lsum[r] = 0.f;
    for (int w = tid; w < N_NODE; w += 256) {
#pragma unroll
        for (int r = 0; r < ADJ_R; r++) {
            float e = __expf(z[r * NP + w] - srow[r]);
            z[r * NP + w] = e;
            lsum[r] += e;
        }
    }
#pragma unroll
    for (int r = 0; r < ADJ_R; r++) {
        red[tid] = lsum[r]; __syncthreads();
        for (int s = 128; s > 0; s >>= 1) { if (tid < s) red[tid] += red[tid + s]; __syncthreads(); }
        if (tid == 0) srow[r] = 0.5f / red[0];
        __syncthreads();
    }
    for (int w = tid; w < NP; w += 256) {
#pragma unroll
        for (int r = 0; r < ADJ_R; r++) {
            int v = r0 + r;
            float val = (w < N_NODE) ? (z[r * NP + w] * srow[r] + ((w == v) ? 0.5f : 0.f)) : 0.f;
            g_Bh[(size_t)v * NP + w] = __float2half_rn(val);
        }
    }
}

// ---------------- kernel 2: start conv on HMMA (2-product) ----------------
__global__ __launch_bounds__(256, 2) void k_conv_mma(const float* __restrict__ bias) {
    extern __shared__ char smem[];
    const uint32_t sbase = smem_u32(smem);
    __half* xw = (__half*)(smem + CV_XW);
    const int tid = threadIdx.x;
    const int wid = tid >> 5, lane = tid & 31;
    const int wm = wid >> 1;
    const int wn = wid & 1;
    const int b  = blockIdx.y;
    const int n0 = blockIdx.x * 128;

#define CV_LOAD_A(ci, stg) do {                                                      \
    _Pragma("unroll")                                                                \
    for (int i = 0; i < 2; i++) {                                                    \
        int idx = tid + i * 256;                                                     \
        int co = idx >> 3, s = idx & 7;                                              \
        uint32_t dst = sbase + CV_A0 + (stg) * CV_A_STG + co * 128 +                 \
                       ((uint32_t)(s ^ (co & 7)) << 4);                              \
        cpa16(dst,            (const char*)(g_Whi + (ci) * CC * 64 + co * 64 + s * 8)); \
        cpa16(dst + CV_A_VAR, (const char*)(g_Wlo + (ci) * CC * 64 + co * 64 + s * 8)); \
    }                                                                                \
} while (0)

#define CV_LOAD_XW(ci, stg) do {                                                     \
    if (tid < 24)                                                                    \
        cpa16(sbase + CV_XW + (stg) * 384 + tid * 16,                                \
              (const char*)(g_Xh + (size_t)b * IN_D * DM + (ci) * DM + n0) + tid * 16); \
} while (0)

#define CV_BUILD_B(stg) do {                                                         \
    const __half* xwp = xw + (stg) * 192;                                            \
    _Pragma("unroll")                                                                \
    for (int i = 0; i < 16; i++) {                                                   \
        int idx = tid + i * 256;                                                     \
        int t = idx >> 6, j2 = idx & 63;                                             \
        int n = j2 * 2;                                                              \
        __half2 hh(xwp[t + n], xwp[t + n + 1]);                                      \
        int s = n >> 3;                                                              \
        uint32_t off = t * 256 + ((uint32_t)(s ^ (t & 7)) << 4) + (j2 & 3) * 4;      \
        *(uint32_t*)(smem + CV_B0 + (stg) * CV_B_STG + off) = *reinterpret_cast<uint32_t*>(&hh); \
    }                                                                                \
} while (0)

    float acc[8][4];
#pragma unroll
    for (int in = 0; in < 8; in++)
#pragma unroll
        for (int q = 0; q < 4; q++) acc[in][q] = 0.f;

    const int a_row = wm * 16 + (lane & 15);
    const int a_jl  = lane >> 4;
    const int b_kl  = ((lane >> 3) & 1) * 8 + (lane & 7);
    const int b_nl  = lane >> 4;

    CV_LOAD_A(0, 0);
    CV_LOAD_XW(0, 0);
    CPA_COMMIT();
    CPA_WAIT(0);
    __syncthreads();
    CV_BUILD_B(0);
    __syncthreads();

    for (int c = 0; c < IN_D; c++) {
        int stg = c & 1, nstg = (c + 1) & 1;
        if (c + 1 < IN_D) { CV_LOAD_A(c + 1, nstg); CV_LOAD_XW(c + 1, nstg); CPA_COMMIT(); }

        uint32_t astg = sbase + CV_A0 + stg * CV_A_STG;
        uint32_t bstg = sbase + CV_B0 + stg * CV_B_STG;
#pragma unroll
        for (int ks = 0; ks < 4; ks++) {
            uint32_t ah[4], al[4], bh[4][4];
            {
                int s = 2 * ks + a_jl;
                uint32_t off = (uint32_t)a_row * 128 + ((uint32_t)(s ^ (a_row & 7)) << 4);
                ldsm4(ah, astg + off);
                ldsm4(al, astg + CV_A_VAR + off);
            }
            int krow = ks * 16 + b_kl;
            uint32_t koff = (uint32_t)krow * 256;
            uint32_t kx = (uint32_t)(krow & 7);
#pragma unroll
            for (int q = 0; q < 4; q++) {
                int ns = wn * 8 + 2 * q + b_nl;
                uint32_t off = koff + ((uint32_t)(ns ^ kx) << 4);
                ldsm4t(bh[q], bstg + off);
            }
#pragma unroll
            for (int p = 0; p < 2; p++) {
#pragma unroll
                for (int in = 0; in < 8; in++) {
                    const uint32_t* af = (p == 1) ? al : ah;
                    mma16816(acc[in], af, &bh[in >> 1][(in & 1) * 2]);
                }
            }
        }
        if (c + 1 < IN_D) {
            CPA_WAIT(0);
            __syncthreads();
            CV_BUILD_B(nstg);
            __syncthreads();
        }
    }

    const int o0 = wm * 16 + (lane >> 2);
    const int o1 = o0 + 8;
    const float b0v = bias[o0], b1v = bias[o1];
#pragma unroll
    for (int in = 0; in < 8; in++) {
        int n = n0 + wn * 64 + in * 8 + (lane & 3) * 2;
        bool ok = (n < N_NODE);
        float v00 = ok ? (acc[in][0] + b0v) : 0.f;
        float v01 = ok ? (acc[in][1] + b0v) : 0.f;
        float v10 = ok ? (acc[in][2] + b1v) : 0.f;
        float v11 = ok ? (acc[in][3] + b1v) : 0.f;
        size_t r0 = (size_t)(b * CC + o0) * NP + n;
        size_t r1 = (size_t)(b * CC + o1) * NP + n;
        __half h0, l0, h1, l1;
        fp16_split(v00, h0, l0); fp16_split(v01, h1, l1);
        *(__half2*)(g_Ahi + r0) = __half2(h0, h1);
        *(__half2*)(g_Alo + r0) = __half2(l0, l1);
        fp16_split(v10, h0, l0); fp16_split(v11, h1, l1);
        *(__half2*)(g_Ahi + r1) = __half2(h0, h1);
        *(__half2*)(g_Alo + r1) = __half2(l0, l1);
    }
#undef CV_LOAD_A
#undef CV_LOAD_XW
#undef CV_BUILD_B
}

// ---------------- kernel 3: mixprop GEMM (256x128 CTA, 4 stages, sync per 2 chunks) --
__global__ __launch_bounds__(512, 1) void k_mix_mma(int src, int dst) {
    extern __shared__ char smem[];
    const uint32_t sbase = smem_u32(smem);

    const int tid = threadIdx.x;
    const int wid = tid >> 5, lane = tid & 31;
    const int wm = wid >> 2;
    const int wn = wid & 3;
    const int m0 = blockIdx.y * TILE_M;
    const int n0 = blockIdx.x * TILE_N;

    const __half* Ahi = g_Ahi + (size_t)src * MROWS * NP;

    const int ar = tid >> 1;
    const int as_ = (tid & 1) * 4;
    const uint32_t aswz = (uint32_t)(ar & 7);
    const int br = tid >> 2;
    const int bs_ = (tid & 3) * 2;
    const uint32_t bswz = (uint32_t)(br & 7);
    const char* gA = (const char*)(Ahi + (size_t)(m0 + ar) * NP) + as_ * 16;
    const char* gB = (const char*)(g_Bh + (size_t)(n0 + br) * NP) + bs_ * 16;

#define LOAD_CHUNK(cidx, buf) do {                                                   \
    uint32_t sb = sbase + (buf) * STAGE_BYTES;                                       \
    size_t go = (size_t)(cidx) * 128;                                                \
    uint32_t sa = sb + OFF_AH + ar * 128;                                            \
    _Pragma("unroll")                                                                \
    for (int j = 0; j < 4; j++) {                                                    \
        uint32_t so = ((uint32_t)(as_ + j) ^ aswz) << 4;                             \
        cpa16(sa + so, gA + go + j * 16);                                            \
    }                                                                                \
    uint32_t sbb = sb + OFF_BH + br * 128;                                           \
    _Pragma("unroll")                                                                \
    for (int j = 0; j < 2; j++) {                                                    \
        uint32_t so = ((uint32_t)(bs_ + j) ^ bswz) << 4;                             \
        cpa16(sbb + so, gB + go + j * 16);                                           \
    }                                                                                \
} while (0)

    float acc[4][4][4];
#pragma unroll
    for (int im = 0; im < 4; im++)
#pragma unroll
        for (int in = 0; in < 4; in++)
#pragma unroll
            for (int q = 0; q < 4; q++) acc[im][in][q] = 0.f;

    const int a_row_l = (lane & 15);
    const int a_jl = lane >> 4;
    const int b_row_l = ((lane >> 4) << 3) + (lane & 7);
    const int b_jl = (lane >> 3) & 1;

#define COMPUTE_CHUNK(buf) do {                                                      \
    uint32_t sb = sbase + (buf) * STAGE_BYTES;                                       \
    _Pragma("unroll")                                                                \
    for (int ks = 0; ks < 4; ks++) {                                                 \
        uint32_t ah[4][4], bh[2][4];                                                 \
        _Pragma("unroll")                                                            \
        for (int im = 0; im < 4; im++) {                                             \
            int row = wm * 64 + im * 16 + a_row_l;                                   \
            uint32_t off = (uint32_t)row * 128 +                                     \
                           ((uint32_t)((2 * ks + a_jl) ^ (row & 7)) << 4);           \
            ldsm4(ah[im], sb + OFF_AH + off);                                        \
        }                                                                            \
        _Pragma("unroll")                                                            \
        for (int inb = 0; inb < 2; inb++) {                                          \
            int row = wn * 32 + inb * 16 + b_row_l;                                  \
            uint32_t off = (uint32_t)row * 128 +                                     \
                           ((uint32_t)((2 * ks + b_jl) ^ (row & 7)) << 4);           \
            ldsm4(bh[inb], sb + OFF_BH + off);                                       \
        }                                                                            \
        _Pragma("unroll")                                                            \
        for (int im = 0; im < 4; im++)                                               \
            _Pragma("unroll")                                                        \
            for (int in = 0; in < 4; in++)                                           \
                mma16816(acc[im][in], ah[im], &bh[in >> 1][(in & 1) * 2]);           \
    }                                                                                \
} while (0)

    LOAD_CHUNK(0, 0); CPA_COMMIT();
    LOAD_CHUNK(1, 1); CPA_COMMIT();

    for (int cc = 0; cc < NCHUNK; cc += 2) {
        __syncthreads();
        if (cc + 2 < NCHUNK) {
            LOAD_CHUNK(cc + 2, (cc + 2) & 3); CPA_COMMIT();
            LOAD_CHUNK(cc + 3, (cc + 3) & 3); CPA_COMMIT();
            CPA_WAIT(2);
        } else {
            CPA_WAIT(0);
        }
        COMPUTE_CHUNK(cc & 3);
        COMPUTE_CHUNK((cc + 1) & 3);
    }

    // epilogue: C = ALPHA*(h0 hi+lo) + BETA*acc -> fp16 hi only
    const __half* Xh = g_Ahi;
    const __half* Xl = g_Alo;
    __half* Hh = g_Ahi + (size_t)dst * MROWS * NP;

#pragma unroll
    for (int im = 0; im < 4; im++) {
#pragma unroll
        for (int half = 0; half < 2; half++) {
            int m = m0 + wm * 64 + im * 16 + (lane >> 2) + half * 8;
            size_t rowo = (size_t)m * NP;
#pragma unroll
            for (int in = 0; in < 4; in++) {
                int n = n0 + wn * 32 + in * 8 + (lane & 3) * 2;
                float d0 = acc[im][in][half * 2 + 0];
                float d1 = acc[im][in][half * 2 + 1];
                __half2 xh = *(const __half2*)(Xh + rowo + n);
                __half2 xl = *(const __half2*)(Xl + rowo + n);
                float x0 = __half2float(xh.x) + __half2float(xl.x);
                float x1 = __half2float(xh.y) + __half2float(xl.y);
                float o0 = ALPHA_C * x0 + BETA_C * d0;
                float o1 = ALPHA_C * x1 + BETA_C * d1;
                *(__half2*)(Hh + rowo + n) =
                    __half2(__float2half_rn(o0), __float2half_rn(o1));
            }
        }
    }
#undef LOAD_CHUNK
#undef COMPUTE_CHUNK
}

// ---------------- kernel 4: MLP on HMMA (2-product) + GELU + end dot ----------------
__global__ __launch_bounds__(256) void k_mlp_mma(const float* __restrict__ bmlp,
                                                 const float* __restrict__ wend,
                                                 const float* __restrict__ bend) {
    extern __shared__ char smem[];
    __shared__ float red[4][128];
    const uint32_t sbase = smem_u32(smem);
    const int tid = threadIdx.x;
    const int wid = tid >> 5, lane = tid & 31;
    const int wm = wid >> 1;
    const int wn = wid & 1;
    const int b  = blockIdx.y;
    const int n0 = blockIdx.x * 128;

#pragma unroll
    for (int i = 0; i < 8; i++) {
        int idx = tid + i * 256;
        int o = idx >> 5, s = idx & 31;
        uint32_t phys = (uint32_t)(s ^ (o & 15));
        uint32_t dst = sbase + o * 512 + phys * 16;
        cpa16(dst + MLP_A_HI, (const char*)(g_Mhi + o * 256 + s * 8));
        cpa16(dst + MLP_A_LO, (const char*)(g_Mlo + o * 256 + s * 8));
    }

#define LOAD_BCH(chunk, stg) do {                                                        \
    const __half* HBh = g_Ahi + ((size_t)(chunk) * MROWS + b * 64) * NP + n0;            \
    _Pragma("unroll")                                                                    \
    for (int i = 0; i < 4; i++) {                                                        \
        int idx = tid + i * 256;                                                         \
        int k = idx >> 4, s = idx & 15;                                                  \
        uint32_t phys = (uint32_t)(s ^ (k & 7));                                         \
        uint32_t dst = sbase + MLP_B_BASE + (stg) * MLP_B_STG + k * 256 + phys * 16;     \
        cpa16(dst, (const char*)HBh + (size_t)k * NP * 2 + s * 16);                      \
    }                                                                                    \
} while (0)

    float acc[8][4];
#pragma unroll
    for (int in = 0; in < 8; in++)
#pragma unroll
        for (int q = 0; q < 4; q++) acc[in][q] = 0.f;

    const int a_row = wm * 16 + (lane & 15);
    const int a_jl  = lane >> 4;
    const int b_kl  = ((lane >> 3) & 1) * 8 + (lane & 7);
    const int b_nl  = lane >> 4;

    LOAD_BCH(0, 0); CPA_COMMIT();

    for (int chunk = 0; chunk < 4; chunk++) {
        CPA_WAIT(0);
        __syncthreads();
        if (chunk < 3) { LOAD_BCH(chunk + 1, (chunk + 1) & 1); CPA_COMMIT(); }
        uint32_t bstg = sbase + MLP_B_BASE + (chunk & 1) * MLP_B_STG;

#pragma unroll
        for (int ks = 0; ks < 4; ks++) {
            int ksg = chunk * 4 + ks;
            uint32_t ah[4], al[4], bh[4][4];
            {
                int s = 2 * ksg + a_jl;
                uint32_t off = (uint32_t)a_row * 512 + ((uint32_t)(s ^ (a_row & 15)) << 4);
                ldsm4(ah, sbase + MLP_A_HI + off);
                ldsm4(al, sbase + MLP_A_LO + off);
            }
            int krow = ks * 16 + b_kl;
            uint32_t koff = (uint32_t)krow * 256;
            uint32_t kx = (uint32_t)(krow & 7);
#pragma unroll
            for (int q = 0; q < 4; q++) {
                int ns = wn * 8 + 2 * q + b_nl;
                uint32_t off = koff + ((uint32_t)(ns ^ kx) << 4);
                ldsm4t(bh[q], bstg + off);
            }
#pragma unroll
            for (int p = 0; p < 2; p++) {
#pragma unroll
                for (int in = 0; in < 8; in++) {
                    const uint32_t* af = (p == 1) ? al : ah;
                    mma16816(acc[in], af, &bh[in >> 1][(in & 1) * 2]);
                }
            }
        }
        __syncthreads();
    }

    const int o0 = wm * 16 + (lane >> 2);
    const int o1 = o0 + 8;
    const float bm0 = bmlp[o0], bm1 = bmlp[o1];
    const float we0 = wend[o0], we1 = wend[o1];

#pragma unroll
    for (int in = 0; in < 8; in++) {
        float g00 = gelu_exact(acc[in][0] + bm0);
        float g01 = gelu_exact(acc[in][1] + bm0);
        float g10 = gelu_exact(acc[in][2] + bm1);
        float g11 = gelu_exact(acc[in][3] + bm1);
        float p0 = we0 * g00 + we1 * g10;
        float p1 = we0 * g01 + we1 * g11;
#pragma unroll
        for (int d = 4; d <= 16; d <<= 1) {
            p0 += __shfl_xor_sync(0xFFFFFFFF, p0, d);
            p1 += __shfl_xor_sync(0xFFFFFFFF, p1, d);
        }
        if (lane < 4) {
            red[wm][wn * 64 + in * 8 + lane * 2 + 0] = p0;
            red[wm][wn * 64 + in * 8 + lane * 2 + 1] = p1;
        }
    }
    __syncthreads();
    if (tid < 128) {
        int n = n0 + tid;
        float s = bend[0] + red[0][tid] + red[1][tid] + red[2][tid] + red[3][tid];
        g_Sh[(size_t)b * NP + n] = __float2half_rn((n < N_NODE) ? s : 0.f);
    }
#undef LOAD_BCH
}

// ---------------- kernel 5: final linear on HMMA ----------------
__global__ __launch_bounds__(256) void k_lin_mma(const float* __restrict__ blin) {
    extern __shared__ char smem[];
    const uint32_t sbase = smem_u32(smem);
    const int tid = threadIdx.x;
    const int wid = tid >> 5, lane = tid & 31;
    const int wm = wid >> 1;
    const int wn = wid & 1;
    const int n0 = blockIdx.x * LIN_TN;

#define LIN_LOAD(cidx, stg) do {                                                     \
    _Pragma("unroll")                                                                \
    for (int i = 0; i < 2; i++) {                                                    \
        int idx = tid + i * 256;                                                     \
        int row = idx >> 3, s = idx & 7;                                             \
        uint32_t so = ((uint32_t)(s ^ (row & 7)) << 4);                              \
        cpa16(sbase + (stg) * LIN_STG + row * 128 + so,                              \
              (const char*)(g_Sh + (size_t)row * NP) + (size_t)(cidx) * 128 + s * 16); \
    }                                                                                \
    {                                                                                \
        int row = tid >> 3, s = tid & 7;                                             \
        uint32_t so = ((uint32_t)(s ^ (row & 7)) << 4);                              \
        cpa16(sbase + (stg) * LIN_STG + LIN_A_BYTES + row * 128 + so,                \
              (const char*)(g_Wl + (size_t)(n0 + row) * NP) + (size_t)(cidx) * 128 + s * 16); \
    }                                                                                \
} while (0)

    float acc[2][4];
#pragma unroll
    for (int in = 0; in < 2; in++)
#pragma unroll
        for (int q = 0; q < 4; q++) acc[in][q] = 0.f;

    const int a_row_l = (lane & 15);
    const int a_jl = lane >> 4;
    const int b_row_l = ((lane >> 4) << 3) + (lane & 7);
    const int b_jl = (lane >> 3) & 1;

    LIN_LOAD(0, 0); CPA_COMMIT();

    for (int c = 0; c < 32; c++) {
        CPA_WAIT(0);
        __syncthreads();
        if (c + 1 < 32) { LIN_LOAD(c + 1, (c + 1) & 1); CPA_COMMIT(); }
        uint32_t astg = sbase + (c & 1) * LIN_STG;
        uint32_t bstg = astg + LIN_A_BYTES;
#pragma unroll
        for (int ks = 0; ks < 4; ks++) {
            uint32_t ah[4], bh[4];
            {
                int row = wm * 16 + a_row_l;
                uint32_t off = (uint32_t)row * 128 +
                               ((uint32_t)((2 * ks + a_jl) ^ (row & 7)) << 4);
                ldsm4(ah, astg + off);
            }
            {
                int row = wn * 16 + b_row_l;
                uint32_t off = (uint32_t)row * 128 +
                               ((uint32_t)((2 * ks + b_jl) ^ (row & 7)) << 4);
                ldsm4(bh, bstg + off);
            }
#pragma unroll
            for (int in = 0; in < 2; in++)
                mma16816(acc[in], ah, &bh[in * 2]);
        }
        __syncthreads();
    }

#pragma unroll
    for (int in = 0; in < 2; in++) {
        int d = n0 + wn * 16 + in * 8 + (lane & 3) * 2;
        int b0 = wm * 16 + (lane >> 2), b1 = b0 + 8;
        float bl0 = blin[d], bl1 = blin[d + 1];
        g_Y[(size_t)b0 * DM + d]     = acc[in][0] + bl0;
        g_Y[(size_t)b0 * DM + d + 1] = acc[in][1] + bl1;
        g_Y[(size_t)b1 * DM + d]     = acc[in][2] + bl0;
        g_Y[(size_t)b1 * DM + d + 1] = acc[in][3] + bl1;
    }
#undef LIN_LOAD
}

// ---------------- kernel 6: layernorm ----------------
__global__ void k_ln(const float* __restrict__ gam, const float* __restrict__ bet,
                     float* __restrict__ out) {
    int b = blockIdx.x;
    int tid = threadIdx.x;
    __shared__ float red[256];
    const float* y = g_Y + (size_t)b * DM;

    float s = 0.f;
    for (int d = tid; d < DM; d += 256) s += y[d];
    red[tid] = s; __syncthreads();
    for (int st = 128; st > 0; st >>= 1) { if (tid < st) red[tid] += red[tid + st]; __syncthreads(); }
    float mu = red[0] / DM;
    __syncthreads();

    float v = 0.f;
    for (int d = tid; d < DM; d += 256) { float t = y[d] - mu; v += t * t; }
    red[tid] = v; __syncthreads();
    for (int st = 128; st > 0; st >>= 1) { if (tid < st) red[tid] += red[tid + st]; __syncthreads(); }
    float rinv = rsqrtf(red[0] / DM + 1e-5f);

    for (int d = tid; d < DM; d += 256)
        out[(size_t)b * DM + d] = (y[d] - mu) * rinv * gam[d] + bet[d];
}

// ---------------- launch (forked-capture: conv/prepl overlap adj/mix) ----------------
extern "C" void kernel_launch(void* const* d_in, const int* in_sizes, int n_in,
                              void* d_out, int out_size) {
    const float* x       = (const float*)d_in[0];
    const float* nv1     = (const float*)d_in[1];
    const float* nv2     = (const float*)d_in[2];
    const float* w_start = (const float*)d_in[3];
    const float* b_start = (const float*)d_in[4];
    const float* w_mlp   = (const float*)d_in[5];
    const float* b_mlp   = (const float*)d_in[6];
    const float* w_end   = (const float*)d_in[7];
    const float* b_end   = (const float*)d_in[8];
    const float* w_lin   = (const float*)d_in[9];
    const float* b_lin   = (const float*)d_in[10];
    const float* ln_g    = (const float*)d_in[11];
    const float* ln_b    = (const float*)d_in[12];
    float* out = (float*)d_out;

    static bool init = false;
    static cudaStream_t s2;
    static cudaEvent_t e_prep, e_conv, e_lin;
    if (!init) {
        cudaStreamCreateWithFlags(&s2, cudaStreamNonBlocking);
        cudaEventCreateWithFlags(&e_prep, cudaEventDisableTiming);
        cudaEventCreateWithFlags(&e_conv, cudaEventDisableTiming);
        cudaEventCreateWithFlags(&e_lin,  cudaEventDisableTiming);
        cudaFuncSetAttribute(k_mix_mma,  cudaFuncAttributeMaxDynamicSharedMemorySize, MIX_SMEM);
        cudaFuncSetAttribute(k_mlp_mma,  cudaFuncAttributeMaxDynamicSharedMemorySize, MLP_SMEM);
        cudaFuncSetAttribute(k_conv_mma, cudaFuncAttributeMaxDynamicSharedMemorySize, CV_SMEM);
        cudaFuncSetAttribute(k_adj,      cudaFuncAttributeMaxDynamicSharedMemorySize, ADJ_SMEM);
        cudaFuncSetAttribute(k_lin_mma,  cudaFuncAttributeMaxDynamicSharedMemorySize, LIN_SMEM);
        init = true;
    }

    // stream 0: prep1 -> adj     stream s2: (after prep1) conv -> prepl
    k_prep1<<<PREP1_BLOCKS, 256>>>(w_start, x, w_mlp);
    cudaEventRecord(e_prep, 0);
    k_adj<<<ADJ_BLOCKS, 256, ADJ_SMEM>>>(nv1, nv2);

    cudaStreamWaitEvent(s2, e_prep, 0);
    k_conv_mma<<<dim3(NP / 128, BATCH), 256, CV_SMEM, s2>>>(b_start);
    cudaEventRecord(e_conv, s2);
    k_prepl<<<DM, 256, 0, s2>>>(w_lin);
    cudaEventRecord(e_lin, s2);

    cudaStreamWaitEvent(0, e_conv, 0);      // mix needs adj (stream 0) + conv
    dim3 mixg(NP / TILE_N, MROWS / TILE_M);
    k_mix_mma<<<mixg, 512, MIX_SMEM>>>(0, 1);
    k_mix_mma<<<mixg, 512, MIX_SMEM>>>(1, 2);
    k_mix_mma<<<mixg, 512, MIX_SMEM>>>(2, 3);
    k_mlp_mma<<<dim3(NP / 128, BATCH), 256, MLP_SMEM>>>(b_mlp, w_end, b_end);
    cudaStreamWaitEvent(0, e_lin, 0);       // lin needs prepl (joins s2)
    k_lin_mma<<<NP / LIN_TN, 256, LIN_SMEM>>>(b_lin);
    k_ln<<<BATCH, 256>>>(ln_g, ln_b, out);
}